// round 16
// baseline (speedup 1.0000x reference)
#include <cuda_runtime.h>
#include <cuda_fp16.h>
#include <math.h>

// ---------------------------------------------------------------------------
// Struct2SeqGCN as ONE persistent kernel. tf32 mma.sync GEMM (no-cvt fill),
// tanh-based sigmoid, fp16 (v,d) lerp tables, 2-warps-per-node CSR agg with
// deterministic 2-atomic combine. N=20000, E=320000, H=128, 4 layers.
// ---------------------------------------------------------------------------

#define NMAX     20000
#define EMAX     320000
#define HID      128
#define NBINS    2048
#define LMAX     4
#define NBLOCKS  444            // 3 blocks/SM on 148 SMs
#define NTHREADS 256

// ------------------------- static scratch (no allocs) ----------------------
__device__ __align__(16) float  g_h   [NMAX * HID];
__device__ __align__(16) float  g_A2  [NMAX * 256];        // [Af|As] fp32
__device__ __align__(16) __half g_Bh  [NMAX * 256];        // [Bf|Bs] fp16
__device__ __align__(16) float  g_agg [NMAX * HID];
__device__ __align__(16) __half g_Tf16[(size_t)LMAX * NBINS * 256]; // (v,d)
__device__ __align__(16) __half g_Ts16[(size_t)LMAX * NBINS * 256];
__device__ int   g_degcur[2 * NMAX];
__device__ int   g_rowptr[NMAX + 1];
__device__ __align__(8) int2 g_edge[EMAX];                 // (src, pos-bits)
__device__ __align__(16) float g_part[NBLOCKS * 2 * HID];
__device__ __align__(16) float g_bns [2 * HID];

// grid barrier (zero-initialized; gen monotonic across replays)
__device__ volatile unsigned g_bar_gen;
__device__ unsigned          g_bar_cnt;

__device__ __forceinline__ void grid_sync() {
    __syncthreads();
    if (threadIdx.x == 0) {
        __threadfence();
        unsigned gen = g_bar_gen;
        if (atomicAdd(&g_bar_cnt, 1u) == NBLOCKS - 1) {
            g_bar_cnt = 0;
            __threadfence();
            g_bar_gen = gen + 1;
        } else {
            while (g_bar_gen == gen) { __nanosleep(64); }
        }
        __threadfence();
    }
    __syncthreads();
}

// sigmoid via single-MUFU tanh: sigmoid(x) = 0.5*tanh(x/2)+0.5
__device__ __forceinline__ float fsigmoid(float x) {
    float t;
    asm("tanh.approx.f32 %0, %1;" : "=f"(t) : "f"(x * 0.5f));
    return fmaf(t, 0.5f, 0.5f);
}
__device__ __forceinline__ float fsoftplus(float x) {
    return fmaxf(x, 0.0f) + __logf(1.0f + __expf(-fabsf(x)));
}

__device__ __forceinline__ void mma_tf32(float* d, const unsigned* a, const unsigned* b) {
    asm volatile(
        "mma.sync.aligned.m16n8k8.row.col.f32.tf32.tf32.f32 "
        "{%0,%1,%2,%3}, {%4,%5,%6,%7}, {%8,%9}, {%0,%1,%2,%3};"
        : "+f"(d[0]), "+f"(d[1]), "+f"(d[2]), "+f"(d[3])
        : "r"(a[0]), "r"(a[1]), "r"(a[2]), "r"(a[3]), "r"(b[0]), "r"(b[1]));
}

// ----------------------- packed per-edge register set ----------------------
struct EP {
    uint4 tf, ts;   // 4x half2 (v,d) per gate for this lane's 4 channels
    uint2 b1, b2;   // 4x half Bf, 4x half Bs
    float t;
};

__device__ __forceinline__ void ep_load(int idx, int lane, size_t lrow, EP& r) {
    int2 e = g_edge[idx];
    float p = __int_as_float(e.y);
    int k = (int)p;
    r.t = p - (float)k;
    const __half* tf = g_Tf16 + (lrow + (size_t)k) * 256;
    const __half* ts = g_Ts16 + (lrow + (size_t)k) * 256;
    r.tf = *(const uint4*)(tf + 8 * lane);
    r.ts = *(const uint4*)(ts + 8 * lane);
    const __half* B = g_Bh + (size_t)e.x * 256;
    r.b1 = *(const uint2*)(B + 4 * lane);
    r.b2 = *(const uint2*)(B + 128 + 4 * lane);
}

__device__ __forceinline__ void ep_acc(const EP& r, const float4 af, const float4 as_,
                                       float4& acc) {
    const __half2* tf = (const __half2*)&r.tf;
    const __half2* ts = (const __half2*)&r.ts;
    const __half2* b1 = (const __half2*)&r.b1;
    const __half2* b2 = (const __half2*)&r.b2;
    float2 bfa = __half22float2(b1[0]), bfb = __half22float2(b1[1]);
    float2 bsa = __half22float2(b2[0]), bsb = __half22float2(b2[1]);
    float2 vd;
    vd = __half22float2(tf[0]); float f0 = af.x + bfa.x + vd.x + r.t * vd.y;
    vd = __half22float2(tf[1]); float f1 = af.y + bfa.y + vd.x + r.t * vd.y;
    vd = __half22float2(tf[2]); float f2 = af.z + bfb.x + vd.x + r.t * vd.y;
    vd = __half22float2(tf[3]); float f3 = af.w + bfb.y + vd.x + r.t * vd.y;
    vd = __half22float2(ts[0]); float s0 = as_.x + bsa.x + vd.x + r.t * vd.y;
    vd = __half22float2(ts[1]); float s1 = as_.y + bsa.y + vd.x + r.t * vd.y;
    vd = __half22float2(ts[2]); float s2 = as_.z + bsb.x + vd.x + r.t * vd.y;
    vd = __half22float2(ts[3]); float s3 = as_.w + bsb.y + vd.x + r.t * vd.y;
    acc.x += fsigmoid(f0) * fsoftplus(s0);
    acc.y += fsigmoid(f1) * fsoftplus(s1);
    acc.z += fsigmoid(f2) * fsoftplus(s2);
    acc.w += fsigmoid(f3) * fsoftplus(s3);
}

// ---------------------------------------------------------------------------
__global__ __launch_bounds__(NTHREADS, 3)
void mega_kernel(const float* __restrict__ x, const int* __restrict__ ei,
                 const float* __restrict__ dist,
                 const float* __restrict__ Wn, const float* __restrict__ bnode,
                 const float* __restrict__ Wf, const float* __restrict__ bfp,
                 const float* __restrict__ Ws, const float* __restrict__ bsp,
                 const float* __restrict__ bng, const float* __restrict__ bnb,
                 const float* __restrict__ lng, const float* __restrict__ lnb,
                 const float* __restrict__ lnog, const float* __restrict__ lnob,
                 const float* __restrict__ Wfc, const float* __restrict__ bfc,
                 float* __restrict__ out, int N, int E, int L)
{
    // pool: GEMM A tf32 [2][128][20] (5120 u) + B tf32 [2][16][68] (2176 u)
    // reused by table build and P8 (Wfc cache)
    __shared__ __align__(16) unsigned s_pool[7296];   // 29184 B
    __shared__ __align__(16) float sBN[2048];         //  8192 B

    const int tid   = threadIdx.x;
    const int gtid  = blockIdx.x * NTHREADS + tid;
    const int nth   = NBLOCKS * NTHREADS;
    const int lane  = tid & 31;
    const int wid   = tid >> 5;
    const int gwarp = blockIdx.x * (NTHREADS / 32) + wid;
    const int nwarp = NBLOCKS * (NTHREADS / 32);
    const int Z     = 2 * HID + 16;                  // 272

    // ================= P0: zero degcur + agg, embed =========================
    for (int i = gtid; i < 2 * NMAX; i += nth) g_degcur[i] = 0;
    for (int i = gtid; i < NMAX * HID; i += nth) g_agg[i] = 0.f;

    for (int i = gtid; i < N * HID; i += nth) {
        int n = i >> 7, c = i & 127;
        float acc = bnode[c];
        #pragma unroll
        for (int k = 0; k < 6; k++) acc += x[n * 6 + k] * Wn[k * HID + c];
        g_h[i] = acc;
    }

    // ---- P0b: (v,d) fp16 tables, 16 output bins per job --------------------
    for (int job = blockIdx.x; job < L * (NBINS / 16); job += NBLOCKS) {
        __syncthreads();
        int l     = job / (NBINS / 16);
        int chunk = job - l * (NBINS / 16);
        int b0    = chunk * 16;
        const float* Wfe = Wf + (size_t)l * Z * HID + 256 * HID;
        const float* Wse = Ws + (size_t)l * Z * HID + 256 * HID;
        const float* bfl = bfp + l * HID;
        const float* bsl = bsp + l * HID;
        float* sm0 = (float*)s_pool;          // 17*128
        float* sm1 = sm0 + 2176;

        for (int idx = tid; idx < 17 * 128; idx += NTHREADS) {
            int bb = idx >> 7, c = idx & 127;
            float d  = (float)(b0 + bb) * (8.0f / (float)NBINS);
            float af = bfl[c], as = bsl[c];
            #pragma unroll
            for (int g = 0; g < 16; g++) {
                float off = (float)g * (8.0f / 15.0f);
                float t = d - off;
                float e = expf(-1.7578125f * t * t);   // COEFF = -0.5/(8/15)^2
                af += e * Wfe[g * HID + c];
                as += e * Wse[g * HID + c];
            }
            sm0[idx] = af;
            sm1[idx] = as;
        }
        __syncthreads();
        for (int idx = tid; idx < 16 * 128; idx += NTHREADS) {
            int bb = idx >> 7, c = idx & 127;
            size_t o = ((size_t)l * NBINS + b0 + bb) * 128 + c;
            float vf = sm0[idx], df = sm0[idx + 128] - vf;
            float vs = sm1[idx], ds = sm1[idx + 128] - vs;
            ((__half2*)g_Tf16)[o] = __floats2half2_rn(vf, df);
            ((__half2*)g_Ts16)[o] = __floats2half2_rn(vs, ds);
        }
    }
    grid_sync();

    // ================= P1: degree histogram =================================
    for (int e = gtid; e < E; e += nth) atomicAdd(&g_degcur[ei[E + e]], 1);
    grid_sync();

    // ================= P2: exclusive scan (block 0, warp 0) =================
    if (blockIdx.x == 0 && wid == 0) {
        int carry = 0;
        for (int base = 0; base < N; base += 32) {
            int i = base + lane;
            int v = (i < N) ? g_degcur[i] : 0;
            int xs = v;
            #pragma unroll
            for (int d = 1; d < 32; d <<= 1) {
                int y = __shfl_up_sync(0xffffffffu, xs, d);
                if (lane >= d) xs += y;
            }
            if (i < N) g_rowptr[i] = carry + xs - v;
            carry += __shfl_sync(0xffffffffu, xs, 31);
        }
        if (lane == 0) g_rowptr[N] = carry;
    }
    grid_sync();

    // ================= P3: scatter edges into CSR ===========================
    for (int e = gtid; e < E; e += nth) {
        int s = ei[e];
        int d = ei[E + e];
        int pos = g_rowptr[d] + atomicAdd(&g_degcur[NMAX + d], 1);
        float p = dist[e] * ((float)NBINS / 8.0f);
        p = fminf(fmaxf(p, 0.0f), (float)NBINS - 0.001f);
        g_edge[pos] = make_int2(s, __float_as_int(p));
    }
    grid_sync();

    const int mtiles = (N + 127) / 128;
    const int gjobs  = 4 * mtiles * 2;   // parts x M-tiles x 2 N-halves

    unsigned* sA = s_pool;          // [2][128*20]
    unsigned* sB = s_pool + 5120;   // [2][16*68]

    // ========================== layer loop ==================================
    for (int l = 0; l < L; l++) {
        const float* Wfl = Wf + (size_t)l * Z * HID;
        const float* Wsl = Ws + (size_t)l * Z * HID;

        // ---- P4: node precompute GEMM via tf32 mma (128x64 tiles) ----
        for (int job = blockIdx.x; job < gjobs; job += NBLOCKS) {
            __syncthreads();
            int part = job / (2 * mtiles);       // 0:Af 1:Bf 2:As 3:Bs
            int rem  = job - part * 2 * mtiles;
            int m0   = (rem >> 1) * 128;
            int n0   = (rem & 1) * 64;
            const float* Bp = ((part < 2) ? Wfl : Wsl) + (part & 1) * (HID * HID);

            const int wm = wid & 3;              // 4 warps over M (32 rows each)
            const int wn = wid >> 2;             // 2 warps over N (32 cols each)
            float acc[2][4][4];
            #pragma unroll
            for (int a = 0; a < 2; a++)
                #pragma unroll
                for (int b = 0; b < 4; b++)
                    #pragma unroll
                    for (int c = 0; c < 4; c++) acc[a][b][c] = 0.f;

            // chunk copy: raw fp32 bits fed to tf32 mma (HW truncates mantissa)
            auto copy_chunk = [&](int kc, int buf) {
                unsigned* dA = sA + buf * 2560;
                #pragma unroll
                for (int ii = 0; ii < 2; ii++) {
                    int i = tid + ii * 256;          // 512 float4 jobs
                    int row = i >> 2, kq = (i & 3) * 4;
                    int gm = m0 + row;
                    float4 v = (gm < N) ? *(const float4*)(g_h + (size_t)gm * HID + kc + kq)
                                        : make_float4(0.f, 0.f, 0.f, 0.f);
                    unsigned* p = dA + row * 20 + kq;
                    p[0] = __float_as_uint(v.x); p[1] = __float_as_uint(v.y);
                    p[2] = __float_as_uint(v.z); p[3] = __float_as_uint(v.w);
                }
                unsigned* dB = sB + buf * 1088;
                {
                    int kr = tid >> 4, nq = (tid & 15) * 4;   // 256 float4 jobs
                    float4 v = *(const float4*)(Bp + (size_t)(kc + kr) * HID + n0 + nq);
                    unsigned* p = dB + kr * 68 + nq;
                    p[0] = __float_as_uint(v.x); p[1] = __float_as_uint(v.y);
                    p[2] = __float_as_uint(v.z); p[3] = __float_as_uint(v.w);
                }
            };

            copy_chunk(0, 0);
            __syncthreads();

            #pragma unroll
            for (int c = 0; c < 8; c++) {
                int buf = c & 1;
                if (c < 7) copy_chunk((c + 1) * 16, buf ^ 1);
                const unsigned* cA = sA + buf * 2560;
                const unsigned* cB = sB + buf * 1088;
                #pragma unroll
                for (int ks = 0; ks < 2; ks++) {
                    int k8 = ks * 8;
                    unsigned afr[2][4];
                    #pragma unroll
                    for (int mi = 0; mi < 2; mi++) {
                        int rb = wm * 32 + mi * 16 + (lane >> 2);
                        int cb = k8 + (lane & 3);
                        afr[mi][0] = cA[rb * 20 + cb];
                        afr[mi][1] = cA[(rb + 8) * 20 + cb];
                        afr[mi][2] = cA[rb * 20 + cb + 4];
                        afr[mi][3] = cA[(rb + 8) * 20 + cb + 4];
                    }
                    unsigned bfr[4][2];
                    #pragma unroll
                    for (int ni = 0; ni < 4; ni++) {
                        int nb = wn * 32 + ni * 8 + (lane >> 2);
                        int kb = k8 + (lane & 3);
                        bfr[ni][0] = cB[kb * 68 + nb];
                        bfr[ni][1] = cB[(kb + 4) * 68 + nb];
                    }
                    #pragma unroll
                    for (int mi = 0; mi < 2; mi++)
                        #pragma unroll
                        for (int ni = 0; ni < 4; ni++)
                            mma_tf32(acc[mi][ni], afr[mi], bfr[ni]);
                }
                __syncthreads();
            }

            // epilogue: parts 0/2 -> fp32 g_A2, parts 1/3 -> fp16 g_Bh
            int off = (part & 1) ? ((part == 1) ? 0 : 128) : (part ? 128 : 0);
            #pragma unroll
            for (int mi = 0; mi < 2; mi++) {
                int gr = m0 + wm * 32 + mi * 16 + (lane >> 2);
                #pragma unroll
                for (int ni = 0; ni < 4; ni++) {
                    int col = n0 + wn * 32 + ni * 8 + (lane & 3) * 2;
                    float* d = acc[mi][ni];
                    if ((part & 1) == 0) {
                        if (gr < N)
                            *(float2*)(g_A2 + (size_t)gr * 256 + off + col) =
                                make_float2(d[0], d[1]);
                        if (gr + 8 < N)
                            *(float2*)(g_A2 + (size_t)(gr + 8) * 256 + off + col) =
                                make_float2(d[2], d[3]);
                    } else {
                        if (gr < N)
                            *(__half2*)(g_Bh + (size_t)gr * 256 + off + col) =
                                __floats2half2_rn(d[0], d[1]);
                        if (gr + 8 < N)
                            *(__half2*)(g_Bh + (size_t)(gr + 8) * 256 + off + col) =
                                __floats2half2_rn(d[2], d[3]);
                    }
                }
            }
        }
        grid_sync();

        // ---- P5: edge aggregation — 2 warps per node, interleaved edges ----
        // Combine via exactly 2 atomicAdds onto zeroed g_agg: bit-deterministic
        // (RN(a+b) == RN(b+a); init is exact 0).
        {
            const float4* A2v = (const float4*)g_A2;   // 64 float4 per node
            const size_t lrow = (size_t)l * NBINS;
            const int gpair = gwarp >> 1;
            const int npair = nwarp >> 1;
            const int half  = gwarp & 1;

            for (int node = gpair; node < N; node += npair) {
                float4 af  = A2v[(size_t)node * 64 + lane];
                float4 as_ = A2v[(size_t)node * 64 + 32 + lane];
                float4 acc = make_float4(0.f, 0.f, 0.f, 0.f);

                int beg = g_rowptr[node] + half, end = g_rowptr[node + 1];
                if (beg < end) {
                    EP cur, nxt;
                    ep_load(beg, lane, lrow, cur);
                    for (int i = beg; i < end; i += 2) {
                        if (i + 2 < end) ep_load(i + 2, lane, lrow, nxt);
                        ep_acc(cur, af, as_, acc);
                        cur = nxt;
                    }
                }
                float* dst = g_agg + (size_t)node * HID + lane * 4;
                atomicAdd(dst + 0, acc.x);
                atomicAdd(dst + 1, acc.y);
                atomicAdd(dst + 2, acc.z);
                atomicAdd(dst + 3, acc.w);
            }
        }
        grid_sync();

        // ---- P5b: BN partials from combined agg ----
        {
            float ps0 = 0, ps1 = 0, ps2 = 0, ps3 = 0;
            float pq0 = 0, pq1 = 0, pq2 = 0, pq3 = 0;
            for (int node = gwarp; node < N; node += nwarp) {
                float4 a = ((const float4*)g_agg)[(size_t)node * 32 + lane];
                ps0 += a.x; pq0 += a.x * a.x;
                ps1 += a.y; pq1 += a.y * a.y;
                ps2 += a.z; pq2 += a.z * a.z;
                ps3 += a.w; pq3 += a.w * a.w;
            }
            __syncthreads();
            sBN[wid * 256 + lane * 4 + 0] = ps0; sBN[wid * 256 + 128 + lane * 4 + 0] = pq0;
            sBN[wid * 256 + lane * 4 + 1] = ps1; sBN[wid * 256 + 128 + lane * 4 + 1] = pq1;
            sBN[wid * 256 + lane * 4 + 2] = ps2; sBN[wid * 256 + 128 + lane * 4 + 2] = pq2;
            sBN[wid * 256 + lane * 4 + 3] = ps3; sBN[wid * 256 + 128 + lane * 4 + 3] = pq3;
            __syncthreads();
            {
                float s = 0.f;
                #pragma unroll
                for (int w = 0; w < 8; w++) s += sBN[w * 256 + tid];
                g_part[blockIdx.x * 256 + tid] = s;
            }
        }
        grid_sync();

        // ---- P6: BN finalize (block 0) ----
        if (blockIdx.x == 0 && tid < 128) {
            float s = 0.f, q = 0.f;
            for (int i = 0; i < NBLOCKS; i++) {
                s += g_part[i * 256 + tid];
                q += g_part[i * 256 + 128 + tid];
            }
            float invN = 1.0f / (float)N;
            float mu   = s * invN;
            float var  = fmaxf(q * invN - mu * mu, 0.0f);
            float sc   = bng[l * HID + tid] * rsqrtf(var + 1e-5f);
            g_bns[tid]       = sc;
            g_bns[128 + tid] = bnb[l * HID + tid] - mu * sc;
        }
        grid_sync();

        // ---- P7: BN-apply + residual + LN + ReLU + residual; re-zero agg ----
        {
            const float* lngl = lng + l * HID;
            const float* lnbl = lnb + l * HID;
            for (int node = gwarp; node < N; node += nwarp) {
                float4 a  = ((const float4*)g_agg)[(size_t)node * 32 + lane];
                float4 hv = ((const float4*)g_h)  [(size_t)node * 32 + lane];
                // zero for next layer's atomic accumulation
                ((float4*)g_agg)[(size_t)node * 32 + lane] =
                    make_float4(0.f, 0.f, 0.f, 0.f);
                float4 sc = ((const float4*)g_bns)[lane];
                float4 sh = ((const float4*)g_bns)[32 + lane];

                float cx = a.x * sc.x + sh.x + hv.x;
                float cy = a.y * sc.y + sh.y + hv.y;
                float cz = a.z * sc.z + sh.z + hv.z;
                float cw = a.w * sc.w + sh.w + hv.w;

                float sum = cx + cy + cz + cw;
                #pragma unroll
                for (int d = 16; d; d >>= 1) sum += __shfl_xor_sync(0xffffffffu, sum, d);
                float m = sum * (1.0f / 128.0f);

                float dx = cx - m, dy = cy - m, dz = cz - m, dw = cw - m;
                float q = dx * dx + dy * dy + dz * dz + dw * dw;
                #pragma unroll
                for (int d = 16; d; d >>= 1) q += __shfl_xor_sync(0xffffffffu, q, d);
                float rr = rsqrtf(q * (1.0f / 128.0f) + 1e-5f);

                float4 g4 = ((const float4*)lngl)[lane];
                float4 b4 = ((const float4*)lnbl)[lane];
                float4 o;
                o.x = fmaxf(dx * rr * g4.x + b4.x, 0.f) + hv.x;
                o.y = fmaxf(dy * rr * g4.y + b4.y, 0.f) + hv.y;
                o.z = fmaxf(dz * rr * g4.z + b4.z, 0.f) + hv.z;
                o.w = fmaxf(dw * rr * g4.w + b4.w, 0.f) + hv.w;
                ((float4*)g_h)[(size_t)node * 32 + lane] = o;
            }
        }
        grid_sync();
    }

    // ================= P8: final LN + FC (warp/node) ========================
    {
        float* sWfc = (float*)s_pool;          // 2688 floats, fits
        for (int i = tid; i < HID * 21; i += NTHREADS) sWfc[i] = Wfc[i];
        __syncthreads();

        for (int node = gwarp; node < N; node += nwarp) {
            float4 hv = ((const float4*)g_h)[(size_t)node * 32 + lane];
            float sum = hv.x + hv.y + hv.z + hv.w;
            #pragma unroll
            for (int d = 16; d; d >>= 1) sum += __shfl_xor_sync(0xffffffffu, sum, d);
            float m = sum * (1.0f / 128.0f);

            float dx = hv.x - m, dy = hv.y - m, dz = hv.z - m, dw = hv.w - m;
            float q = dx * dx + dy * dy + dz * dz + dw * dw;
            #pragma unroll
            for (int d = 16; d; d >>= 1) q += __shfl_xor_sync(0xffffffffu, q, d);
            float rr = rsqrtf(q * (1.0f / 128.0f) + 1e-5f);

            float4 g4 = ((const float4*)lnog)[lane];
            float4 b4 = ((const float4*)lnob)[lane];
            float h0 = dx * rr * g4.x + b4.x;
            float h1 = dy * rr * g4.y + b4.y;
            float h2 = dz * rr * g4.z + b4.z;
            float h3 = dw * rr * g4.w + b4.w;

            const float* wp = sWfc + (lane * 4) * 21;
            #pragma unroll
            for (int cls = 0; cls < 21; cls++) {
                float p = h0 * wp[cls] + h1 * wp[21 + cls]
                        + h2 * wp[42 + cls] + h3 * wp[63 + cls];
                #pragma unroll
                for (int d = 16; d; d >>= 1) p += __shfl_xor_sync(0xffffffffu, p, d);
                if (lane == 0) out[(size_t)node * 21 + cls] = p + bfc[cls];
            }
        }
    }
}

// ------------------------------- launch ------------------------------------
extern "C" void kernel_launch(void* const* d_in, const int* in_sizes, int n_in,
                              void* d_out, int out_size) {
    const float* x     = (const float*)d_in[0];
    const int*   ei    = (const int*)  d_in[1];
    const float* dist  = (const float*)d_in[2];
    const float* Wn    = (const float*)d_in[3];
    const float* bn    = (const float*)d_in[4];
    const float* Wf    = (const float*)d_in[5];
    const float* bf    = (const float*)d_in[6];
    const float* Ws    = (const float*)d_in[7];
    const float* bs    = (const float*)d_in[8];
    const float* bng   = (const float*)d_in[9];
    const float* bnb   = (const float*)d_in[10];
    const float* lng   = (const float*)d_in[11];
    const float* lnb   = (const float*)d_in[12];
    const float* lnog  = (const float*)d_in[13];
    const float* lnob  = (const float*)d_in[14];
    const float* Wfc   = (const float*)d_in[15];
    const float* bfc   = (const float*)d_in[16];

    const int N = in_sizes[0] / 6;        // 20000
    const int E = in_sizes[2];            // 320000
    int L = in_sizes[6] / HID;            // 4
    if (L > LMAX) L = LMAX;

    mega_kernel<<<NBLOCKS, NTHREADS>>>(x, ei, dist, Wn, bn, Wf, bf, Ws, bs,
                                       bng, bnb, lng, lnb, lnog, lnob, Wfc, bfc,
                                       (float*)d_out, N, E, L);
}